// round 13
// baseline (speedup 1.0000x reference)
#include <cuda_runtime.h>

// out[b] = sum_k x[b,k] * S[k],  S[k] = sum_h W[h,k]   (scale 0.5*2.0 == 1.0)
// FUSED single kernel: 256 colsum CTAs + 256 matvec CTAs, chunk-pipelined via
// device flags so the W-stream and x-stream overlap on every SM.

#define BATCH  4096
#define IN     4096
#define HID    4096
#define NCHUNK 4
#define CK4    256          // float4 columns per chunk
#define NCS    256          // colsum CTAs
#define NMV    256          // matvec CTAs

struct Glob { float S[IN]; int done[NCHUNK]; };
__device__ Glob g;          // zeroed by one memset node per launch

__device__ __forceinline__ int ld_acquire(const int* p) {
    int v;
    asm volatile("ld.acquire.gpu.b32 %0, [%1];" : "=r"(v) : "l"(p));
    return v;
}

__global__ void __launch_bounds__(256, 4) fused_kernel(const float* __restrict__ x,
                                                       const float* __restrict__ W,
                                                       float* __restrict__ out) {
    __shared__ float part[16][257];
    const int tid  = threadIdx.x;
    const int lane = tid & 31;
    const int wid  = tid >> 5;
    const int stride4 = IN / 4;

    if (blockIdx.x < NCS) {
        // ── colsum role: rows [16b, 16b+16), chunks in order ──
        const float4* Wv = reinterpret_cast<const float4*>(W);
        long rbase = (long)(blockIdx.x * 16) * stride4;

        for (int c = 0; c < NCHUNK; c++) {
            int k4 = c * CK4 + tid;
            float4 acc = make_float4(0.f, 0.f, 0.f, 0.f);
            #pragma unroll
            for (int gq = 0; gq < 2; gq++) {
                float4 v[8];
                #pragma unroll
                for (int r = 0; r < 8; r++)
                    v[r] = __ldcs(&Wv[rbase + (long)(gq * 8 + r) * stride4 + k4]);
                #pragma unroll
                for (int r = 0; r < 8; r++) {
                    acc.x += v[r].x; acc.y += v[r].y;
                    acc.z += v[r].z; acc.w += v[r].w;
                }
            }
            float* dst = &g.S[k4 * 4];
            asm volatile("red.global.add.v4.f32 [%0], {%1, %2, %3, %4};"
                         :: "l"(dst), "f"(acc.x), "f"(acc.y), "f"(acc.z), "f"(acc.w)
                         : "memory");
            __threadfence();                 // make REDG visible before flagging
            __syncthreads();                 // all warps of this CTA done with chunk c
            if (tid == 0) atomicAdd(&g.done[c], 1);
        }
    } else {
        // ── matvec role: rows [16m, 16m+16), waits per chunk ──
        int m = blockIdx.x - NCS;
        const float4* xv = reinterpret_cast<const float4*>(x);
        long rbase = (long)(m * 16) * stride4;

        #pragma unroll
        for (int r = 0; r < 16; r++) part[r][tid] = 0.f;   // thread owns slot

        for (int c = 0; c < NCHUNK; c++) {
            if (tid == 0) {
                while (ld_acquire(&g.done[c]) < NCS) __nanosleep(64);
            }
            __syncthreads();                 // chunk c of S is complete + visible

            int k4 = c * CK4 + tid;
            float4 s4 = reinterpret_cast<const float4*>(g.S)[k4];  // L2-hot

            #pragma unroll
            for (int gq = 0; gq < 2; gq++) {
                float4 v[8];
                #pragma unroll
                for (int r = 0; r < 8; r++)
                    v[r] = __ldcs(&xv[rbase + (long)(gq * 8 + r) * stride4 + k4]);
                #pragma unroll
                for (int r = 0; r < 8; r++) {
                    float p = fmaf(v[r].x, s4.x,
                              fmaf(v[r].y, s4.y,
                              fmaf(v[r].z, s4.z, v[r].w * s4.w)));
                    part[gq * 8 + r][tid] += p;
                }
            }
        }
        __syncthreads();

        // Deferred reduce: warp w handles rows w and w+8. Direct store.
        #pragma unroll
        for (int rr = 0; rr < 2; rr++) {
            int r = wid + rr * 8;
            float s = 0.f;
            #pragma unroll
            for (int j = 0; j < 8; j++)
                s += part[r][lane + j * 32];
            #pragma unroll
            for (int off = 16; off > 0; off >>= 1)
                s += __shfl_xor_sync(0xFFFFFFFFu, s, off);
            if (lane == 0) out[m * 16 + r] = s;
        }
    }
}

extern "C" void kernel_launch(void* const* d_in, const int* in_sizes, int n_in,
                              void* d_out, int out_size) {
    const float* x = (const float*)d_in[0];
    const float* W = (const float*)d_in[1];
    float* out = (float*)d_out;

    void* gp = nullptr;
    cudaGetSymbolAddress(&gp, g);
    cudaMemsetAsync(gp, 0, sizeof(Glob));   // zeros S and done[] every replay

    fused_kernel<<<NCS + NMV, 256>>>(x, W, out);
}